// round 3
// baseline (speedup 1.0000x reference)
#include <cuda_runtime.h>
#include <cuda_fp16.h>
#include <math.h>

#define N_ITERS 12
#define NB 4
#define NH 384
#define NW 512
#define HW (NH * NW)

#define BLK_W 32
#define BLK_H 16
#define NTHREADS (BLK_W * BLK_H)
#define HALO 8
#define TILE_W (BLK_W + 2 * HALO)     // 48
#define TILE_H (BLK_H + 2 * HALO)     // 32
#define TILE_STRIDE (TILE_W + 1)      // 49 half2 -> decorrelate banks
#define GRID_X (NW / BLK_W)           // 16
#define GRID_Y (NH / BLK_H)           // 24
#define NBLOCKS (GRID_X * GRID_Y * NB) // 1536

__device__ float g_part[N_ITERS * NBLOCKS];

// Cold path: sample escaped the +/-8 halo (never happens for N(0,1) flow).
// Full fp32 bilinear with zero-padding semantics, straight from global.
__device__ __noinline__ float3 global_bilinear(
    const float* __restrict__ f1b, int x0, int y0,
    float wx0, float wx1, float wy0, float wy1)
{
    const bool vx0 = (unsigned)x0 < (unsigned)NW;
    const bool vx1 = (unsigned)(x0 + 1) < (unsigned)NW;
    const bool vy0 = (unsigned)y0 < (unsigned)NH;
    const bool vy1 = (unsigned)(y0 + 1) < (unsigned)NH;
    const float w00 = (vy0 && vx0) ? wy0 * wx0 : 0.0f;
    const float w01 = (vy0 && vx1) ? wy0 * wx1 : 0.0f;
    const float w10 = (vy1 && vx0) ? wy1 * wx0 : 0.0f;
    const float w11 = (vy1 && vx1) ? wy1 * wx1 : 0.0f;
    const int x0c = min(max(x0, 0), NW - 1);
    const int x1c = min(max(x0 + 1, 0), NW - 1);
    const int y0c = min(max(y0, 0), NH - 1);
    const int y1c = min(max(y0 + 1, 0), NH - 1);
    float3 r;
    float* rp = &r.x;
    #pragma unroll
    for (int c = 0; c < 3; c++) {
        const float* p = f1b + c * HW;
        rp[c] = p[y0c * NW + x0c] * w00 + p[y0c * NW + x1c] * w01
              + p[y1c * NW + x0c] * w10 + p[y1c * NW + x1c] * w11;
    }
    return r;
}

__global__ __launch_bounds__(NTHREADS, 2) void warp_psnr_kernel(
    const float* __restrict__ flow,
    const float* __restrict__ frame1,
    const float* __restrict__ frame2)
{
    // 3 channel planes; cell [r][c] = half2( f1[r][c], f1[r+1][c] ).
    __shared__ __half2 tile[3 * TILE_H * TILE_STRIDE];

    const int tx = threadIdx.x;
    const int ty = threadIdx.y;
    const int bx = blockIdx.x * BLK_W;
    const int by = blockIdx.y * BLK_H;
    const int b  = blockIdx.z;
    const int w = bx + tx;
    const int h = by + ty;
    const int tid = ty * BLK_W + tx;

    const float* __restrict__ f1b = frame1 + (size_t)b * 3 * HW;

    // ---- Fill tile: clamp-to-edge reads (clamped texels only pair with zero
    // weights on the fast path; zero-padding handled via weights). ----
    for (int t = tid; t < 3 * TILE_H * TILE_W; t += NTHREADS) {
        const int ch = t / (TILE_H * TILE_W);
        const int rc = t - ch * (TILE_H * TILE_W);
        const int r = rc / TILE_W;
        const int c = rc - r * TILE_W;
        const int gy0 = min(max(by - HALO + r, 0), NH - 1);
        const int gy1 = min(max(by - HALO + r + 1, 0), NH - 1);
        const int gx  = min(max(bx - HALO + c, 0), NW - 1);
        const float v0 = f1b[ch * HW + gy0 * NW + gx];
        const float v1 = f1b[ch * HW + gy1 * NW + gx];
        tile[ch * (TILE_H * TILE_STRIDE) + r * TILE_STRIDE + c] =
            __floats2half2_rn(v0, v1);
    }
    __syncthreads();

    // ---- frame2 pixel in registers across all 12 iterations ----
    const int pix = h * NW + w;
    const float* f2 = frame2 + (size_t)b * 3 * HW + pix;
    const float r2x = f2[0];
    const float r2y = f2[HW];
    const float r2z = f2[2 * HW];

    const float hf = (float)h, wf = (float)w;
    const float* flp = flow + (size_t)b * 2 * HW + pix;

    // Validity math only needed for blocks touching the image border.
    const bool border = (blockIdx.x == 0) | (blockIdx.x == GRID_X - 1) |
                        (blockIdx.y == 0) | (blockIdx.y == GRID_Y - 1);

    float sums[N_ITERS];

    #pragma unroll
    for (int i = 0; i < N_ITERS; i++) {
        const float fy = flp[(size_t)i * NB * 2 * HW];
        const float fx = flp[(size_t)i * NB * 2 * HW + HW];

        const float px = wf + fx;
        const float py = hf + fy;
        const float x0f = floorf(px);
        const float y0f = floorf(py);
        const float wx1 = px - x0f;
        const float wy1 = py - y0f;
        const float wx0 = 1.0f - wx1;
        const float wy0 = 1.0f - wy1;

        const int x0 = (int)x0f;
        const int y0 = (int)y0f;

        float w00, w01, w10, w11;
        if (border) {
            const bool vx0 = (unsigned)x0 < (unsigned)NW;
            const bool vx1 = (unsigned)(x0 + 1) < (unsigned)NW;
            const bool vy0 = (unsigned)y0 < (unsigned)NH;
            const bool vy1 = (unsigned)(y0 + 1) < (unsigned)NH;
            w00 = (vy0 && vx0) ? wy0 * wx0 : 0.0f;
            w01 = (vy0 && vx1) ? wy0 * wx1 : 0.0f;
            w10 = (vy1 && vx0) ? wy1 * wx0 : 0.0f;
            w11 = (vy1 && vx1) ? wy1 * wx1 : 0.0f;
        } else {
            w00 = wy0 * wx0;
            w01 = wy0 * wx1;
            w10 = wy1 * wx0;
            w11 = wy1 * wx1;
        }

        const int sx = x0 - bx + HALO;
        const int sy = y0 - by + HALO;

        float ex, ey, ez;
        if ((unsigned)sx < (unsigned)(TILE_W - 1) &&
            (unsigned)sy < (unsigned)(TILE_H - 1)) {
            const int idx = sy * TILE_STRIDE + sx;
            // channel 0
            const __half2* p0 = tile + idx;
            const float2 a0 = __half22float2(p0[0]);   // (v00, v10)
            const float2 b0 = __half22float2(p0[1]);   // (v01, v11)
            // channel 1
            const __half2* p1 = p0 + TILE_H * TILE_STRIDE;
            const float2 a1 = __half22float2(p1[0]);
            const float2 b1 = __half22float2(p1[1]);
            // channel 2
            const __half2* p2 = p1 + TILE_H * TILE_STRIDE;
            const float2 a2 = __half22float2(p2[0]);
            const float2 b2 = __half22float2(p2[1]);

            ex = a0.x * w00 + b0.x * w01 + a0.y * w10 + b0.y * w11;
            ey = a1.x * w00 + b1.x * w01 + a1.y * w10 + b1.y * w11;
            ez = a2.x * w00 + b2.x * w01 + a2.y * w10 + b2.y * w11;
        } else {
            const float3 e = global_bilinear(f1b, x0, y0, wx0, wx1, wy0, wy1);
            ex = e.x; ey = e.y; ez = e.z;
        }

        const float dx = ex - r2x;
        const float dy = ey - r2y;
        const float dz = ez - r2z;
        sums[i] = fmaf(dx, dx, fmaf(dy, dy, dz * dz));
    }

    // ---- Block reduction -> per-block partial (no atomics, no init) ----
    __shared__ float red[N_ITERS][16];
    const int lane = tid & 31;
    const int wid  = tid >> 5;

    #pragma unroll
    for (int i = 0; i < N_ITERS; i++) {
        float s = sums[i];
        s += __shfl_down_sync(0xffffffffu, s, 16);
        s += __shfl_down_sync(0xffffffffu, s, 8);
        s += __shfl_down_sync(0xffffffffu, s, 4);
        s += __shfl_down_sync(0xffffffffu, s, 2);
        s += __shfl_down_sync(0xffffffffu, s, 1);
        if (lane == 0) red[i][wid] = s;
    }
    __syncthreads();

    if (tid < N_ITERS) {
        float t = 0.0f;
        #pragma unroll
        for (int ww = 0; ww < 16; ww++) t += red[tid][ww];
        const int bid = (blockIdx.z * GRID_Y + blockIdx.y) * GRID_X + blockIdx.x;
        g_part[tid * NBLOCKS + bid] = t;
    }
}

// Final: reduce 1536 partials per iteration, PSNR, cascading weights, loss.
__global__ __launch_bounds__(N_ITERS * 32) void loss_kernel(float* __restrict__ out) {
    __shared__ float contrib[N_ITERS];
    const int i = threadIdx.x >> 5;       // iteration index 0..11
    const int lane = threadIdx.x & 31;

    float s = 0.0f;
    for (int k = lane; k < NBLOCKS; k += 32) s += g_part[i * NBLOCKS + k];
    s += __shfl_down_sync(0xffffffffu, s, 16);
    s += __shfl_down_sync(0xffffffffu, s, 8);
    s += __shfl_down_sync(0xffffffffu, s, 4);
    s += __shfl_down_sync(0xffffffffu, s, 2);
    s += __shfl_down_sync(0xffffffffu, s, 1);

    if (lane == 0) {
        const float inv_n = 1.0f / (float)(NB * 3 * HW);
        const float mse = s * inv_n;
        const float psnr = -10.0f * log10f(mse);
        const float wgt = powf(0.85f, (float)(N_ITERS - i));
        contrib[i] = psnr * wgt;
    }
    __syncthreads();
    if (threadIdx.x == 0) {
        float loss = 0.0f;
        #pragma unroll
        for (int k = 0; k < N_ITERS; k++) loss += contrib[k];
        out[0] = -loss;
    }
}

extern "C" void kernel_launch(void* const* d_in, const int* in_sizes, int n_in,
                              void* d_out, int out_size) {
    const float* flow   = (const float*)d_in[0];  // [12,4,2,384,512]
    const float* frame1 = (const float*)d_in[1];  // [4,3,384,512]
    const float* frame2 = (const float*)d_in[2];  // [4,3,384,512]
    float* out = (float*)d_out;
    (void)in_sizes; (void)n_in; (void)out_size;

    dim3 block(BLK_W, BLK_H);
    dim3 grid(GRID_X, GRID_Y, NB);
    warp_psnr_kernel<<<grid, block>>>(flow, frame1, frame2);

    loss_kernel<<<1, N_ITERS * 32>>>(out);
}

// round 4
// speedup vs baseline: 1.0441x; 1.0441x over previous
#include <cuda_runtime.h>
#include <math.h>

#define N_ITERS 12
#define NB 4
#define NH 384
#define NW 512
#define HW (NH * NW)

#define BLK_W 32
#define BLK_H 16
#define NTHREADS (BLK_W * BLK_H)
#define HALO 8
#define TILE_W (BLK_W + 2 * HALO)     // 48
#define TILE_H (BLK_H + 2 * HALO)     // 32
#define TILE_STRIDE (TILE_W + 1)      // 49 float4
#define GRID_X (NW / BLK_W)           // 16
#define GRID_Y (NH / BLK_H)           // 24
#define ITERS_PER_BLK 6
#define NZ (NB * (N_ITERS / ITERS_PER_BLK))         // 8
#define TOT_BLOCKS (GRID_X * GRID_Y * NZ)           // 3072

__device__ float g_sums[N_ITERS];        // zero at load; reset by last block
__device__ unsigned int g_ticket = 0;    // reset by last block

// Cold path: sample escaped the +/-8 halo (statistically never for N(0,1)
// flow, but required for correctness robustness). Zero-padding semantics.
__device__ __noinline__ float3 global_bilinear(
    const float* __restrict__ f1b, int x0, int y0,
    float wx0, float wx1, float wy0, float wy1)
{
    const bool vx0 = (unsigned)x0 < (unsigned)NW;
    const bool vx1 = (unsigned)(x0 + 1) < (unsigned)NW;
    const bool vy0 = (unsigned)y0 < (unsigned)NH;
    const bool vy1 = (unsigned)(y0 + 1) < (unsigned)NH;
    const float w00 = (vy0 && vx0) ? wy0 * wx0 : 0.0f;
    const float w01 = (vy0 && vx1) ? wy0 * wx1 : 0.0f;
    const float w10 = (vy1 && vx0) ? wy1 * wx0 : 0.0f;
    const float w11 = (vy1 && vx1) ? wy1 * wx1 : 0.0f;
    const int x0c = min(max(x0, 0), NW - 1);
    const int x1c = min(max(x0 + 1, 0), NW - 1);
    const int y0c = min(max(y0, 0), NH - 1);
    const int y1c = min(max(y0 + 1, 0), NH - 1);
    float3 r;
    float* rp = &r.x;
    #pragma unroll
    for (int c = 0; c < 3; c++) {
        const float* p = f1b + c * HW;
        rp[c] = p[y0c * NW + x0c] * w00 + p[y0c * NW + x1c] * w01
              + p[y1c * NW + x0c] * w10 + p[y1c * NW + x1c] * w11;
    }
    return r;
}

__global__ __launch_bounds__(NTHREADS) void warp_psnr_kernel(
    const float* __restrict__ flow,
    const float* __restrict__ frame1,
    const float* __restrict__ frame2,
    float* __restrict__ out)
{
    __shared__ float4 tile[TILE_H * TILE_STRIDE];

    const int tx = threadIdx.x;
    const int ty = threadIdx.y;
    const int bx = blockIdx.x * BLK_W;
    const int by = blockIdx.y * BLK_H;
    const int z  = blockIdx.z;             // 0..7
    const int b     = z >> 1;              // batch
    const int half  = z & 1;               // iteration slab
    const int i0    = half * ITERS_PER_BLK;
    const int w = bx + tx;
    const int h = by + ty;
    const int tid = ty * BLK_W + tx;

    const float* __restrict__ f1b = frame1 + (size_t)b * 3 * HW;

    // ---- Fill frame1 tile (clamp-to-edge; clamped texels only pair with
    // zero weights on the fast path). ----
    for (int t = tid; t < TILE_H * TILE_W; t += NTHREADS) {
        const int r = t / TILE_W;
        const int c = t - r * TILE_W;
        const int gy = min(max(by - HALO + r, 0), NH - 1);
        const int gx = min(max(bx - HALO + c, 0), NW - 1);
        const int g = gy * NW + gx;
        float4 v;
        v.x = f1b[g];
        v.y = f1b[HW + g];
        v.z = f1b[2 * HW + g];
        v.w = 0.0f;
        tile[r * TILE_STRIDE + c] = v;
    }
    __syncthreads();

    // ---- frame2 pixel in registers across the 6 iterations ----
    const int pix = h * NW + w;
    const float* f2 = frame2 + (size_t)b * 3 * HW + pix;
    const float r2x = f2[0];
    const float r2y = f2[HW];
    const float r2z = f2[2 * HW];

    const float hf = (float)h, wf = (float)w;
    const float* flp = flow + ((size_t)i0 * NB + b) * 2 * HW + pix;

    const bool border = (blockIdx.x == 0) | (blockIdx.x == GRID_X - 1) |
                        (blockIdx.y == 0) | (blockIdx.y == GRID_Y - 1);

    float sums[ITERS_PER_BLK];

    #pragma unroll
    for (int i = 0; i < ITERS_PER_BLK; i++) {
        const float fy = flp[(size_t)i * NB * 2 * HW];
        const float fx = flp[(size_t)i * NB * 2 * HW + HW];

        const float px = wf + fx;
        const float py = hf + fy;
        const float x0f = floorf(px);
        const float y0f = floorf(py);
        const float wx1 = px - x0f;
        const float wy1 = py - y0f;
        const float wx0 = 1.0f - wx1;
        const float wy0 = 1.0f - wy1;

        const int x0 = (int)x0f;
        const int y0 = (int)y0f;

        float w00, w01, w10, w11;
        if (border) {
            const bool vx0 = (unsigned)x0 < (unsigned)NW;
            const bool vx1 = (unsigned)(x0 + 1) < (unsigned)NW;
            const bool vy0 = (unsigned)y0 < (unsigned)NH;
            const bool vy1 = (unsigned)(y0 + 1) < (unsigned)NH;
            w00 = (vy0 && vx0) ? wy0 * wx0 : 0.0f;
            w01 = (vy0 && vx1) ? wy0 * wx1 : 0.0f;
            w10 = (vy1 && vx0) ? wy1 * wx0 : 0.0f;
            w11 = (vy1 && vx1) ? wy1 * wx1 : 0.0f;
        } else {
            w00 = wy0 * wx0;
            w01 = wy0 * wx1;
            w10 = wy1 * wx0;
            w11 = wy1 * wx1;
        }

        const int sx = x0 - bx + HALO;
        const int sy = y0 - by + HALO;

        float ex, ey, ez;
        if ((unsigned)sx < (unsigned)(TILE_W - 1) &&
            (unsigned)sy < (unsigned)(TILE_H - 1)) {
            const float4* r0 = tile + sy * TILE_STRIDE + sx;
            const float4 f00 = r0[0];
            const float4 f01 = r0[1];
            const float4 f10 = r0[TILE_STRIDE];
            const float4 f11 = r0[TILE_STRIDE + 1];
            ex = f00.x * w00 + f01.x * w01 + f10.x * w10 + f11.x * w11;
            ey = f00.y * w00 + f01.y * w01 + f10.y * w10 + f11.y * w11;
            ez = f00.z * w00 + f01.z * w01 + f10.z * w10 + f11.z * w11;
        } else {
            const float3 e = global_bilinear(f1b, x0, y0, wx0, wx1, wy0, wy1);
            ex = e.x; ey = e.y; ez = e.z;
        }

        const float dx = ex - r2x;
        const float dy = ey - r2y;
        const float dz = ez - r2z;
        sums[i] = fmaf(dx, dx, fmaf(dy, dy, dz * dz));
    }

    // ---- Block reduction: shuffle -> shared -> 6 global atomics ----
    __shared__ float red[ITERS_PER_BLK][16];
    __shared__ bool s_last;
    const int lane = tid & 31;
    const int wid  = tid >> 5;

    #pragma unroll
    for (int i = 0; i < ITERS_PER_BLK; i++) {
        float s = sums[i];
        s += __shfl_down_sync(0xffffffffu, s, 16);
        s += __shfl_down_sync(0xffffffffu, s, 8);
        s += __shfl_down_sync(0xffffffffu, s, 4);
        s += __shfl_down_sync(0xffffffffu, s, 2);
        s += __shfl_down_sync(0xffffffffu, s, 1);
        if (lane == 0) red[i][wid] = s;
    }
    __syncthreads();

    if (tid < ITERS_PER_BLK) {
        float t = 0.0f;
        #pragma unroll
        for (int ww = 0; ww < 16; ww++) t += red[tid][ww];
        atomicAdd(&g_sums[i0 + tid], t);
    }
    __syncthreads();

    // ---- Last block computes the loss and resets state for graph replay ----
    if (tid == 0) {
        __threadfence();
        const unsigned int ticket = atomicAdd(&g_ticket, 1u);
        s_last = (ticket == TOT_BLOCKS - 1);
    }
    __syncthreads();

    if (s_last && tid == 0) {
        const float inv_n = 1.0f / (float)(NB * 3 * HW);
        float loss = 0.0f;
        #pragma unroll
        for (int k = 0; k < N_ITERS; k++) {
            const float ssum = atomicAdd(&g_sums[k], 0.0f);   // coherent read
            const float mse = ssum * inv_n;
            const float psnr = -10.0f * log10f(mse);
            const float wgt = powf(0.85f, (float)(N_ITERS - k));
            loss += psnr * wgt;
        }
        out[0] = -loss;
        // reset for the next graph replay
        #pragma unroll
        for (int k = 0; k < N_ITERS; k++) g_sums[k] = 0.0f;
        g_ticket = 0u;
        __threadfence();
    }
}

extern "C" void kernel_launch(void* const* d_in, const int* in_sizes, int n_in,
                              void* d_out, int out_size) {
    const float* flow   = (const float*)d_in[0];  // [12,4,2,384,512]
    const float* frame1 = (const float*)d_in[1];  // [4,3,384,512]
    const float* frame2 = (const float*)d_in[2];  // [4,3,384,512]
    float* out = (float*)d_out;
    (void)in_sizes; (void)n_in; (void)out_size;

    dim3 block(BLK_W, BLK_H);
    dim3 grid(GRID_X, GRID_Y, NZ);
    warp_psnr_kernel<<<grid, block>>>(flow, frame1, frame2, out);
}

// round 6
// speedup vs baseline: 1.1374x; 1.0894x over previous
#include <cuda_runtime.h>
#include <math.h>

#define N_ITERS 12
#define NB 4
#define NH 384
#define NW 512
#define HW (NH * NW)

#define BLK_W 32
#define BLK_H 16
#define NTHREADS (BLK_W * BLK_H)
#define HALO 8
#define TILE_W (BLK_W + 2 * HALO)      // 48
#define TILE_H (BLK_H + 2 * HALO)      // 32
#define TILE_STRIDE (TILE_W + 1)       // 49 floats: (17r+c)%32 spreads banks
#define PLANE (TILE_H * TILE_STRIDE)   // 1568 floats per channel plane
#define GRID_X (NW / BLK_W)            // 16
#define GRID_Y (NH / BLK_H)            // 24
#define TOT_BLOCKS (GRID_X * GRID_Y * NB)  // 1536

__device__ float g_sums[N_ITERS];        // zero-init at load; reset by last block
__device__ unsigned int g_ticket = 0;    // reset by last block

// Cold path: sample escaped the +/-8 halo (statistically never for N(0,1)
// flow, but required for correctness robustness). Zero-padding semantics.
__device__ __noinline__ float3 global_bilinear(
    const float* __restrict__ f1b, int x0, int y0,
    float wx0, float wx1, float wy0, float wy1)
{
    const bool vx0 = (unsigned)x0 < (unsigned)NW;
    const bool vx1 = (unsigned)(x0 + 1) < (unsigned)NW;
    const bool vy0 = (unsigned)y0 < (unsigned)NH;
    const bool vy1 = (unsigned)(y0 + 1) < (unsigned)NH;
    const float w00 = (vy0 && vx0) ? wy0 * wx0 : 0.0f;
    const float w01 = (vy0 && vx1) ? wy0 * wx1 : 0.0f;
    const float w10 = (vy1 && vx0) ? wy1 * wx0 : 0.0f;
    const float w11 = (vy1 && vx1) ? wy1 * wx1 : 0.0f;
    const int x0c = min(max(x0, 0), NW - 1);
    const int x1c = min(max(x0 + 1, 0), NW - 1);
    const int y0c = min(max(y0, 0), NH - 1);
    const int y1c = min(max(y0 + 1, 0), NH - 1);
    float3 r;
    float* rp = &r.x;
    #pragma unroll
    for (int c = 0; c < 3; c++) {
        const float* p = f1b + c * HW;
        rp[c] = p[y0c * NW + x0c] * w00 + p[y0c * NW + x1c] * w01
              + p[y1c * NW + x0c] * w10 + p[y1c * NW + x1c] * w11;
    }
    return r;
}

__global__ __launch_bounds__(NTHREADS, 2) void warp_psnr_kernel(
    const float* __restrict__ flow,
    const float* __restrict__ frame1,
    const float* __restrict__ frame2,
    float* __restrict__ out)
{
    __shared__ float tile[3 * PLANE];     // 18.8 KB: 3 scalar channel planes

    const int tx = threadIdx.x;
    const int ty = threadIdx.y;
    const int bx = blockIdx.x * BLK_W;
    const int by = blockIdx.y * BLK_H;
    const int b  = blockIdx.z;
    const int w = bx + tx;
    const int h = by + ty;
    const int tid = ty * BLK_W + tx;

    const float* __restrict__ f1b = frame1 + (size_t)b * 3 * HW;

    // ---- Fill frame1 tile: 3 scalar planes, clamp-to-edge (clamped texels
    // only ever pair with zero weights on the fast path). Coalesced reads,
    // conflict-free scalar stores. ----
    for (int t = tid; t < TILE_H * TILE_W; t += NTHREADS) {
        const int r = t / TILE_W;
        const int c = t - r * TILE_W;
        const int gy = min(max(by - HALO + r, 0), NH - 1);
        const int gx = min(max(bx - HALO + c, 0), NW - 1);
        const int g = gy * NW + gx;
        const int s = r * TILE_STRIDE + c;
        tile[s]             = f1b[g];
        tile[PLANE + s]     = f1b[HW + g];
        tile[2 * PLANE + s] = f1b[2 * HW + g];
    }
    __syncthreads();

    // ---- frame2 pixel in registers across all 12 iterations ----
    const int pix = h * NW + w;
    const float* f2 = frame2 + (size_t)b * 3 * HW + pix;
    const float r2x = f2[0];
    const float r2y = f2[HW];
    const float r2z = f2[2 * HW];

    const float hf = (float)h, wf = (float)w;
    const float* flp = flow + (size_t)b * 2 * HW + pix;

    // Validity math only needed for blocks touching the image border.
    const bool border = (blockIdx.x == 0) | (blockIdx.x == GRID_X - 1) |
                        (blockIdx.y == 0) | (blockIdx.y == GRID_Y - 1);

    float sums[N_ITERS];

    #pragma unroll
    for (int i = 0; i < N_ITERS; i++) {
        const float fy = flp[(size_t)i * NB * 2 * HW];
        const float fx = flp[(size_t)i * NB * 2 * HW + HW];

        const float px = wf + fx;
        const float py = hf + fy;
        const float x0f = floorf(px);
        const float y0f = floorf(py);
        const float wx1 = px - x0f;
        const float wy1 = py - y0f;
        const float wx0 = 1.0f - wx1;
        const float wy0 = 1.0f - wy1;

        const int x0 = (int)x0f;
        const int y0 = (int)y0f;

        float w00, w01, w10, w11;
        if (border) {
            const bool vx0 = (unsigned)x0 < (unsigned)NW;
            const bool vx1 = (unsigned)(x0 + 1) < (unsigned)NW;
            const bool vy0 = (unsigned)y0 < (unsigned)NH;
            const bool vy1 = (unsigned)(y0 + 1) < (unsigned)NH;
            w00 = (vy0 && vx0) ? wy0 * wx0 : 0.0f;
            w01 = (vy0 && vx1) ? wy0 * wx1 : 0.0f;
            w10 = (vy1 && vx0) ? wy1 * wx0 : 0.0f;
            w11 = (vy1 && vx1) ? wy1 * wx1 : 0.0f;
        } else {
            w00 = wy0 * wx0;
            w01 = wy0 * wx1;
            w10 = wy1 * wx0;
            w11 = wy1 * wx1;
        }

        const int sx = x0 - bx + HALO;
        const int sy = y0 - by + HALO;

        float ex, ey, ez;
        if ((unsigned)sx < (unsigned)(TILE_W - 1) &&
            (unsigned)sy < (unsigned)(TILE_H - 1)) {
            // Single base register + 12 immediate-offset LDS.32 (bank-spread).
            const float* t0 = tile + sy * TILE_STRIDE + sx;
            ex = t0[0]           * w00 + t0[1]               * w01
               + t0[TILE_STRIDE] * w10 + t0[TILE_STRIDE + 1] * w11;
            ey = t0[PLANE]               * w00 + t0[PLANE + 1]               * w01
               + t0[PLANE + TILE_STRIDE] * w10 + t0[PLANE + TILE_STRIDE + 1] * w11;
            ez = t0[2 * PLANE]               * w00 + t0[2 * PLANE + 1]               * w01
               + t0[2 * PLANE + TILE_STRIDE] * w10 + t0[2 * PLANE + TILE_STRIDE + 1] * w11;
        } else {
            const float3 e = global_bilinear(f1b, x0, y0, wx0, wx1, wy0, wy1);
            ex = e.x; ey = e.y; ez = e.z;
        }

        const float dx = ex - r2x;
        const float dy = ey - r2y;
        const float dz = ez - r2z;
        sums[i] = fmaf(dx, dx, fmaf(dy, dy, dz * dz));
    }

    // ---- Block reduction: shuffle -> shared -> 12 global atomics ----
    __shared__ float red[N_ITERS][16];
    __shared__ bool s_last;
    const int lane = tid & 31;
    const int wid  = tid >> 5;

    #pragma unroll
    for (int i = 0; i < N_ITERS; i++) {
        float s = sums[i];
        s += __shfl_down_sync(0xffffffffu, s, 16);
        s += __shfl_down_sync(0xffffffffu, s, 8);
        s += __shfl_down_sync(0xffffffffu, s, 4);
        s += __shfl_down_sync(0xffffffffu, s, 2);
        s += __shfl_down_sync(0xffffffffu, s, 1);
        if (lane == 0) red[i][wid] = s;
    }
    __syncthreads();

    if (tid < N_ITERS) {
        float t = 0.0f;
        #pragma unroll
        for (int ww = 0; ww < 16; ww++) t += red[tid][ww];
        atomicAdd(&g_sums[tid], t);
    }
    __syncthreads();

    // ---- Last block computes the loss and resets state for graph replay ----
    if (tid == 0) {
        __threadfence();
        const unsigned int ticket = atomicAdd(&g_ticket, 1u);
        s_last = (ticket == TOT_BLOCKS - 1);
    }
    __syncthreads();

    if (s_last && tid == 0) {
        const float inv_n = 1.0f / (float)(NB * 3 * HW);
        float loss = 0.0f;
        #pragma unroll
        for (int k = 0; k < N_ITERS; k++) {
            const float ssum = atomicAdd(&g_sums[k], 0.0f);   // coherent read
            const float mse = ssum * inv_n;
            const float psnr = -10.0f * log10f(mse);
            const float wgt = powf(0.85f, (float)(N_ITERS - k));
            loss += psnr * wgt;
        }
        out[0] = -loss;
        // reset for the next graph replay
        #pragma unroll
        for (int k = 0; k < N_ITERS; k++) g_sums[k] = 0.0f;
        g_ticket = 0u;
        __threadfence();
    }
}

extern "C" void kernel_launch(void* const* d_in, const int* in_sizes, int n_in,
                              void* d_out, int out_size) {
    const float* flow   = (const float*)d_in[0];  // [12,4,2,384,512]
    const float* frame1 = (const float*)d_in[1];  // [4,3,384,512]
    const float* frame2 = (const float*)d_in[2];  // [4,3,384,512]
    float* out = (float*)d_out;
    (void)in_sizes; (void)n_in; (void)out_size;

    dim3 block(BLK_W, BLK_H);
    dim3 grid(GRID_X, GRID_Y, NB);
    warp_psnr_kernel<<<grid, block>>>(flow, frame1, frame2, out);
}